// round 13
// baseline (speedup 1.0000x reference)
#include <cuda_runtime.h>
#include <cuda_bf16.h>
#include <math.h>
#include <stdint.h>

#define B_   8
#define DIM  192
#define QKV  576
#define NH   8
#define CH   24
#define H_   128
#define W_   128
#define HW   16384

// Scratch (device globals; zero-initialized bss)
__device__ __align__(16) __nv_bfloat16 g_x_hi[B_ * DIM * HW];
__device__ __align__(16) __nv_bfloat16 g_x_lo[B_ * DIM * HW];
__device__ __align__(16) __nv_bfloat16 g_w_hi[640 * DIM];          // 576 + pad
__device__ __align__(16) __nv_bfloat16 g_w_lo[640 * DIM];
__device__ __align__(16) __nv_bfloat16 g_qk   [B_ * 2 * DIM * HW]; // q/k (hi only)
__device__ __align__(16) __nv_bfloat16 g_v_hi [B_ * DIM * HW];
__device__ __align__(16) __nv_bfloat16 g_v_lo [B_ * DIM * HW];
__device__ __align__(16) __nv_bfloat16 g_dwqk [B_ * 2 * DIM * HW];
__device__ __align__(16) __nv_bfloat16 g_dwv_hi[B_ * DIM * HW];
__device__ __align__(16) __nv_bfloat16 g_dwv_lo[B_ * DIM * HW];
__device__ __align__(16) __nv_bfloat16 g_M_hi[B_ * 256 * DIM];     // 192 + pad rows
__device__ __align__(16) __nv_bfloat16 g_M_lo[B_ * 256 * DIM];
__device__ float g_ssq[B_ * DIM];
__device__ float g_ssk[B_ * DIM];
__device__ float g_S  [B_ * NH * CH * CH];

// ---------------------------------------------------------------------------
__global__ void zero_kernel() {
    int i = blockIdx.x * blockDim.x + threadIdx.x;
    if (i < B_ * NH * CH * CH) g_S[i] = 0.f;
    if (i < B_ * DIM) { g_ssq[i] = 0.f; g_ssk[i] = 0.f; }
}

__device__ __forceinline__ void cvt_split(float x, __nv_bfloat16 &hi, __nv_bfloat16 &lo) {
    hi = __float2bfloat16(x);
    lo = __float2bfloat16(x - __bfloat162float(hi));
}

// fp32 -> bf16 hi/lo planes. which: 0 -> x planes, 1 -> w planes
__global__ __launch_bounds__(256) void split_kernel(
    const float* __restrict__ src, int which, long n4)
{
    __nv_bfloat16* hi = which ? g_w_hi : g_x_hi;
    __nv_bfloat16* lo = which ? g_w_lo : g_x_lo;
    long i = blockIdx.x * (long)blockDim.x + threadIdx.x;
    long stride = (long)gridDim.x * blockDim.x;
    for (; i < n4; i += stride) {
        float4 v = ((const float4*)src)[i];
        __nv_bfloat16 h0,h1,h2,h3,l0,l1,l2,l3;
        cvt_split(v.x,h0,l0); cvt_split(v.y,h1,l1);
        cvt_split(v.z,h2,l2); cvt_split(v.w,h3,l3);
        ((__nv_bfloat162*)hi)[i*2]   = __nv_bfloat162(h0,h1);
        ((__nv_bfloat162*)hi)[i*2+1] = __nv_bfloat162(h2,h3);
        ((__nv_bfloat162*)lo)[i*2]   = __nv_bfloat162(l0,l1);
        ((__nv_bfloat162*)lo)[i*2+1] = __nv_bfloat162(l2,l3);
    }
}

// ---------------------------------------------------------------------------
// bf16 tensor-core GEMM, templated on plane count PL. (R10 config)
// PL=2: 3-term bf16x3.  PL=1: hi*hi only.
// BM=128 BN=128 BK=32, 8 warps, warp tile 64x32, 2-stage cp.async.
// ---------------------------------------------------------------------------
#define BM 128
#define BN 128
#define BK 32
#define LDA_S 40
#define LDB_S 136
#define A_PLANE (BM * LDA_S)
#define B_PLANE (BK * LDB_S)

__device__ __forceinline__ uint32_t cvta_s(const void* p) {
    return (uint32_t)__cvta_generic_to_shared(p);
}
__device__ __forceinline__ void cp_async16(uint32_t saddr, const void* gptr) {
    asm volatile("cp.async.cg.shared.global [%0], [%1], 16;" :: "r"(saddr), "l"(gptr));
}
__device__ __forceinline__ void ldsm4(uint32_t &r0, uint32_t &r1, uint32_t &r2,
                                      uint32_t &r3, uint32_t addr) {
    asm volatile("ldmatrix.sync.aligned.m8n8.x4.shared.b16 {%0,%1,%2,%3}, [%4];"
                 : "=r"(r0), "=r"(r1), "=r"(r2), "=r"(r3) : "r"(addr));
}
__device__ __forceinline__ void ldsm4t(uint32_t &r0, uint32_t &r1, uint32_t &r2,
                                       uint32_t &r3, uint32_t addr) {
    asm volatile("ldmatrix.sync.aligned.m8n8.x4.trans.shared.b16 {%0,%1,%2,%3}, [%4];"
                 : "=r"(r0), "=r"(r1), "=r"(r2), "=r"(r3) : "r"(addr));
}
__device__ __forceinline__ void mma16816(float c[4], uint32_t a0, uint32_t a1,
                                         uint32_t a2, uint32_t a3,
                                         uint32_t b0, uint32_t b1) {
    asm volatile(
        "mma.sync.aligned.m16n8k16.row.col.f32.bf16.bf16.f32 "
        "{%0,%1,%2,%3}, {%4,%5,%6,%7}, {%8,%9}, {%0,%1,%2,%3};"
        : "+f"(c[0]), "+f"(c[1]), "+f"(c[2]), "+f"(c[3])
        : "r"(a0), "r"(a1), "r"(a2), "r"(a3), "r"(b0), "r"(b1));
}

// smem bytes for PL planes (2 stages)
#define GEMM_SMEM(PL) ((2 * (PL) * (A_PLANE + B_PLANE)) * 2)

template <int PL>
__global__ __launch_bounds__(256, 2) void gemm_kernel(
    int mode, int ybase, float* __restrict__ Cext)
{
    extern __shared__ __align__(16) __nv_bfloat16 smem[];
    const int b_base = 2 * PL * A_PLANE;   // elements offset of B region

    const int z = blockIdx.z;
    const int by = ybase + blockIdx.y;
    const __nv_bfloat16 *Ahi, *Alo, *Bhi, *Blo;
    if (mode == 0) {
        Ahi = g_w_hi; Alo = g_w_lo;
        Bhi = g_x_hi + (long)z * DIM * HW;
        Blo = g_x_lo + (long)z * DIM * HW;
    } else {
        Ahi = g_M_hi + (long)z * 256 * DIM;
        Alo = g_M_lo + (long)z * 256 * DIM;
        Bhi = g_dwv_hi + (long)z * DIM * HW;
        Blo = g_dwv_lo + (long)z * DIM * HW;
    }
    Ahi += (long)by * BM * DIM;
    Alo += (long)by * BM * DIM;
    const int bcol = blockIdx.x * BN;

    const int t    = threadIdx.x;
    const int lane = t & 31;
    const int warp = t >> 5;
    const int wm   = (warp >> 2) * 64;
    const int wn   = (warp & 3) * 32;
    const int lr   = lane & 15;
    const int lc   = (lane >> 4) * 8;

    float acc[4][4][4];
    #pragma unroll
    for (int i = 0; i < 4; i++)
        #pragma unroll
        for (int j = 0; j < 4; j++)
            #pragma unroll
            for (int r = 0; r < 4; r++) acc[i][j][r] = 0.f;

    auto cpA = [&](int k0, int stage) {
        #pragma unroll
        for (int j = 0; j < 2 * PL; j++) {
            int id  = t + 256 * j;        // 0 .. 512*PL-1
            int p   = id >> 9;            // plane (0 when PL==1)
            int w   = id & 511;
            int row = w >> 2;
            int cc  = w & 3;
            const __nv_bfloat16* g = (p ? Alo : Ahi) + (long)row * DIM + k0 + cc * 8;
            __nv_bfloat16* s = smem + (stage * PL + p) * A_PLANE + row * LDA_S + cc * 8;
            cp_async16(cvta_s(s), g);
        }
    };
    auto cpB = [&](int k0, int stage) {
        #pragma unroll
        for (int j = 0; j < 2 * PL; j++) {
            int id  = t + 256 * j;
            int p   = id >> 9;
            int w   = id & 511;
            int row = w >> 4;
            int cc  = w & 15;
            const __nv_bfloat16* g = (p ? Blo : Bhi) +
                (long)(k0 + row) * HW + bcol + cc * 8;
            __nv_bfloat16* s = smem + b_base + (stage * PL + p) * B_PLANE +
                               row * LDB_S + cc * 8;
            cp_async16(cvta_s(s), g);
        }
    };

    cpA(0, 0); cpB(0, 0);
    asm volatile("cp.async.commit_group;");

    const int NIT = DIM / BK;   // 6
    for (int i = 0; i < NIT; i++) {
        const int stage = i & 1;
        if (i + 1 < NIT) {
            cpA((i + 1) * BK, stage ^ 1);
            cpB((i + 1) * BK, stage ^ 1);
            asm volatile("cp.async.commit_group;");
            asm volatile("cp.async.wait_group 1;");
        } else {
            asm volatile("cp.async.wait_group 0;");
        }
        __syncthreads();

        const __nv_bfloat16* As[2];
        const __nv_bfloat16* Bs[2];
        #pragma unroll
        for (int p = 0; p < PL; p++) {
            As[p] = smem + (stage * PL + p) * A_PLANE;
            Bs[p] = smem + b_base + (stage * PL + p) * B_PLANE;
        }

        #pragma unroll
        for (int kk = 0; kk < BK; kk += 16) {
            uint32_t a[PL][4][4];
            uint32_t b[PL][2][4];
            #pragma unroll
            for (int p = 0; p < PL; p++) {
                #pragma unroll
                for (int mt = 0; mt < 4; mt++)
                    ldsm4(a[p][mt][0], a[p][mt][1], a[p][mt][2], a[p][mt][3],
                          cvta_s(As[p] + (wm + mt * 16 + lr) * LDA_S + kk + lc));
                #pragma unroll
                for (int nc = 0; nc < 2; nc++)
                    ldsm4t(b[p][nc][0], b[p][nc][1], b[p][nc][2], b[p][nc][3],
                           cvta_s(Bs[p] + (kk + lr) * LDB_S + wn + nc * 16 + lc));
            }
            #pragma unroll
            for (int mt = 0; mt < 4; mt++)
                #pragma unroll
                for (int j = 0; j < 4; j++) {
                    uint32_t bh0 = b[0][j >> 1][(j & 1) * 2];
                    uint32_t bh1 = b[0][j >> 1][(j & 1) * 2 + 1];
                    mma16816(acc[mt][j], a[0][mt][0], a[0][mt][1], a[0][mt][2],
                             a[0][mt][3], bh0, bh1);
                    if constexpr (PL == 2) {
                        uint32_t bl0 = b[1][j >> 1][(j & 1) * 2];
                        uint32_t bl1 = b[1][j >> 1][(j & 1) * 2 + 1];
                        mma16816(acc[mt][j], a[0][mt][0], a[0][mt][1], a[0][mt][2],
                                 a[0][mt][3], bl0, bl1);
                        mma16816(acc[mt][j], a[1][mt][0], a[1][mt][1], a[1][mt][2],
                                 a[1][mt][3], bh0, bh1);
                    }
                }
        }
        __syncthreads();
    }

    const int er = lane >> 2;
    const int ec = (lane & 3) * 2;
    #pragma unroll
    for (int mt = 0; mt < 4; mt++) {
        const int g0 = by * BM + wm + mt * 16;
        if (mode == 1) {
            if (g0 < DIM) {
                float* Cb = Cext + (long)z * DIM * HW;
                #pragma unroll
                for (int j = 0; j < 4; j++) {
                    long base = (long)(g0 + er) * HW + bcol + wn + j * 8 + ec;
                    *(float2*)&Cb[base]          = make_float2(acc[mt][j][0], acc[mt][j][1]);
                    *(float2*)&Cb[base + 8 * HW] = make_float2(acc[mt][j][2], acc[mt][j][3]);
                }
            }
        } else if (g0 < 2 * DIM) {
            __nv_bfloat16* dst = g_qk + (long)z * 2 * DIM * HW;
            #pragma unroll
            for (int j = 0; j < 4; j++) {
                long base = (long)(g0 + er) * HW + bcol + wn + j * 8 + ec;
                *(__nv_bfloat162*)&dst[base] = __nv_bfloat162(
                    __float2bfloat16(acc[mt][j][0]), __float2bfloat16(acc[mt][j][1]));
                *(__nv_bfloat162*)&dst[base + 8 * HW] = __nv_bfloat162(
                    __float2bfloat16(acc[mt][j][2]), __float2bfloat16(acc[mt][j][3]));
            }
        } else if (g0 < 3 * DIM) {
            long voff = (long)z * DIM * HW + (long)(g0 - 2 * DIM) * HW;
            #pragma unroll
            for (int j = 0; j < 4; j++) {
                #pragma unroll
                for (int hrow = 0; hrow < 2; hrow++) {
                    long a2 = voff + (long)(er + hrow * 8) * HW + bcol + wn + j * 8 + ec;
                    float v0 = acc[mt][j][hrow * 2], v1 = acc[mt][j][hrow * 2 + 1];
                    __nv_bfloat16 h0,h1,l0,l1;
                    cvt_split(v0,h0,l0); cvt_split(v1,h1,l1);
                    *(__nv_bfloat162*)&g_v_hi[a2] = __nv_bfloat162(h0,h1);
                    *(__nv_bfloat162*)&g_v_lo[a2] = __nv_bfloat162(l0,l1);
                }
            }
        }
    }
}

// ---------------------------------------------------------------------------
// Depthwise 3x3, dilation 2, pad 2; vectorized fill (uint2 = 4 bf16) and
// vectorized stores (uint2). Branch-free inner via halo smem.
// img: 68 rows x 136 cols fp32; input x [0,128) lives at cols [4,132);
// cols 0..3 and 132..135 are zero halo. Interior float4 stores are at
// (136*ry + 4 + 4*cx)*4 bytes -> 16B aligned.
// ---------------------------------------------------------------------------
#define IMW 136

__device__ __forceinline__ float4 bf4_to_f4(uint2 u) {
    __nv_bfloat162 p0 = *(__nv_bfloat162*)&u.x;
    __nv_bfloat162 p1 = *(__nv_bfloat162*)&u.y;
    return make_float4(__bfloat162float(p0.x), __bfloat162float(p0.y),
                       __bfloat162float(p1.x), __bfloat162float(p1.y));
}

__global__ __launch_bounds__(256) void dwconv_kernel(const float* __restrict__ wdw) {
    __shared__ float img[68 * IMW];    // 36,992 B
    __shared__ float warpsum[8];

    const int blk  = blockIdx.x;
    const int half = blk & 1;
    const int bc   = blk >> 1;
    const int b    = bc / QKV;
    const int ch   = bc % QKV;
    const int r0   = half * 64;
    const bool isqk = (ch < 2 * DIM);

    const int t = threadIdx.x;

    // zero halo columns (0..3 and 132..135) of all 68 rows
    for (int i = t; i < 68 * 8; i += 256) {
        int r = i >> 3, c = i & 7;
        img[r * IMW + ((c < 4) ? c : c + 128)] = 0.f;
    }

    // interior fill: 68 rows x 32 chunks of 4 px, at col 4 + 4*cx
    if (isqk) {
        const __nv_bfloat16* in = g_qk + ((long)b * 2 * DIM + ch) * HW;
        for (int i = t; i < 68 * 32; i += 256) {
            int ry = i >> 5, cx = i & 31;
            int y = r0 - 2 + ry;
            float4 v = make_float4(0.f, 0.f, 0.f, 0.f);
            if (y >= 0 && y < H_)
                v = bf4_to_f4(*(const uint2*)&in[y * W_ + cx * 4]);
            *(float4*)&img[ry * IMW + 4 + cx * 4] = v;
        }
    } else {
        long off = ((long)b * DIM + ch - 2 * DIM) * HW;
        const __nv_bfloat16* inh = g_v_hi + off;
        const __nv_bfloat16* inl = g_v_lo + off;
        for (int i = t; i < 68 * 32; i += 256) {
            int ry = i >> 5, cx = i & 31;
            int y = r0 - 2 + ry;
            float4 v = make_float4(0.f, 0.f, 0.f, 0.f);
            if (y >= 0 && y < H_) {
                float4 h = bf4_to_f4(*(const uint2*)&inh[y * W_ + cx * 4]);
                float4 l = bf4_to_f4(*(const uint2*)&inl[y * W_ + cx * 4]);
                v = make_float4(h.x + l.x, h.y + l.y, h.z + l.z, h.w + l.w);
            }
            *(float4*)&img[ry * IMW + 4 + cx * 4] = v;
        }
    }
    float w[9];
    #pragma unroll
    for (int i = 0; i < 9; i++) w[i] = wdw[ch * 9 + i];
    __syncthreads();

    const int x0  = (t & 31) * 4;
    const int yy0 = t >> 5;
    float ssq = 0.f;

    __nv_bfloat16* outqk = g_dwqk + ((long)b * 2 * DIM + (isqk ? ch : 0)) * HW;
    long voff = isqk ? 0 : ((long)b * DIM + ch - 2 * DIM) * HW;

    for (int yo = yy0; yo < 64; yo += 8) {
        const int y    = r0 + yo;
        const int srow = yo + 2;
        float o[4] = {0.f, 0.f, 0.f, 0.f};
        #pragma unroll
        for (int ky = 0; ky < 3; ky++) {
            // output x = x0+j uses cols (x0+j+2) + {0,2,4}
            const float* row = &img[(srow + 2 * ky - 2) * IMW + x0 + 2];
            float w0 = w[ky * 3], w1 = w[ky * 3 + 1], w2 = w[ky * 3 + 2];
            #pragma unroll
            for (int j = 0; j < 4; j++)
                o[j] += w0 * row[j] + w1 * row[j + 2] + w2 * row[j + 4];
        }
        if (isqk) {
            uint2 pk;
            *(__nv_bfloat162*)&pk.x =
                __nv_bfloat162(__float2bfloat16(o[0]), __float2bfloat16(o[1]));
            *(__nv_bfloat162*)&pk.y =
                __nv_bfloat162(__float2bfloat16(o[2]), __float2bfloat16(o[3]));
            *(uint2*)&outqk[y * W_ + x0] = pk;
            #pragma unroll
            for (int j = 0; j < 4; j++) ssq += o[j] * o[j];
        } else {
            __nv_bfloat16 h[4], l[4];
            #pragma unroll
            for (int j = 0; j < 4; j++) cvt_split(o[j], h[j], l[j]);
            uint2 ph, pl;
            *(__nv_bfloat162*)&ph.x = __nv_bfloat162(h[0], h[1]);
            *(__nv_bfloat162*)&ph.y = __nv_bfloat162(h[2], h[3]);
            *(__nv_bfloat162*)&pl.x = __nv_bfloat162(l[0], l[1]);
            *(__nv_bfloat162*)&pl.y = __nv_bfloat162(l[2], l[3]);
            long a = voff + y * W_ + x0;
            *(uint2*)&g_dwv_hi[a] = ph;
            *(uint2*)&g_dwv_lo[a] = pl;
        }
    }

    if (isqk) {
        #pragma unroll
        for (int off = 16; off; off >>= 1)
            ssq += __shfl_xor_sync(0xffffffffu, ssq, off);
        if ((t & 31) == 0) warpsum[t >> 5] = ssq;
        __syncthreads();
        if (t == 0) {
            float s = 0.f;
            #pragma unroll
            for (int i = 0; i < 8; i++) s += warpsum[i];
            float* dst = (ch < DIM) ? &g_ssq[b * DIM + ch]
                                    : &g_ssk[b * DIM + ch - DIM];
            atomicAdd(dst, s);
        }
    }
}

// ---------------------------------------------------------------------------
#define ATTN_SPLIT 64
#define ATTN_NB (HW / ATTN_SPLIT)   // 256

__global__ __launch_bounds__(64) void attn_partial_kernel() {
    __shared__ float qs[CH][68];
    __shared__ float ks[CH][68];

    const int bh   = blockIdx.y;
    const int b    = bh >> 3, head = bh & 7;
    const long qbase = ((long)b * 2 * DIM + head * CH) * HW;
    const long kbase = ((long)b * 2 * DIM + DIM + head * CH) * HW;
    const int nb = blockIdx.x * ATTN_NB;

    const int t  = threadIdx.x;
    const int cb = (t >> 3) * 3;
    const int db = (t & 7)  * 3;

    float acc[3][3] = {{0.f,0.f,0.f},{0.f,0.f,0.f},{0.f,0.f,0.f}};

    for (int c0 = 0; c0 < ATTN_NB; c0 += 64) {
        __syncthreads();
        for (int i = t; i < CH * 16; i += 64) {
            int row = i >> 4, c4 = (i & 15) * 4;
            uint2 uq = *(const uint2*)&g_dwqk[qbase + (long)row * HW + nb + c0 + c4];
            uint2 uk = *(const uint2*)&g_dwqk[kbase + (long)row * HW + nb + c0 + c4];
            float4 q = bf4_to_f4(uq);
            float4 k = bf4_to_f4(uk);
            *(float4*)&qs[row][c4] = q;
            *(float4*)&ks[row][c4] = k;
        }
        __syncthreads();
        #pragma unroll
        for (int nn = 0; nn < 64; nn += 4) {
            float4 q[3], k[3];
            #pragma unroll
            for (int i = 0; i < 3; i++) q[i] = *(float4*)&qs[cb + i][nn];
            #pragma unroll
            for (int j = 0; j < 3; j++) k[j] = *(float4*)&ks[db + j][nn];
            #pragma unroll
            for (int i = 0; i < 3; i++)
                #pragma unroll
                for (int j = 0; j < 3; j++)
                    acc[i][j] += q[i].x * k[j].x + q[i].y * k[j].y +
                                 q[i].z * k[j].z + q[i].w * k[j].w;
        }
    }
    #pragma unroll
    for (int i = 0; i < 3; i++)
        #pragma unroll
        for (int j = 0; j < 3; j++)
            atomicAdd(&g_S[(bh * CH + cb + i) * CH + db + j], acc[i][j]);
}

// ---------------------------------------------------------------------------
__global__ __launch_bounds__(256) void softmax_m_kernel(
    const float* __restrict__ wproj, const float* __restrict__ temperature)
{
    __shared__ float a[CH][CH];
    __shared__ float rq[CH], rk[CH];

    const int bh = blockIdx.x;
    const int b = bh >> 3, head = bh & 7;
    const int t = threadIdx.x;

    for (int i = t; i < CH * CH; i += 256)
        a[i / CH][i % CH] = g_S[bh * CH * CH + i];
    if (t < CH) {
        float nq = sqrtf(g_ssq[b * DIM + head * CH + t]);
        rq[t] = 1.f / fmaxf(nq, 1e-12f);
        float nk = sqrtf(g_ssk[b * DIM + head * CH + t]);
        rk[t] = 1.f / fmaxf(nk, 1e-12f);
    }
    __syncthreads();

    if (t < CH) {
        const float temp = temperature[head];
        float row[CH];
        float m = -1e30f;
        #pragma unroll
        for (int d = 0; d < CH; d++) {
            float v = a[t][d] * rq[t] * rk[d] * temp;
            row[d] = v;
            m = fmaxf(m, v);
        }
        float s = 0.f;
        #pragma unroll
        for (int d = 0; d < CH; d++) { row[d] = expf(row[d] - m); s += row[d]; }
        float inv = 1.f / s;
        #pragma unroll
        for (int d = 0; d < CH; d++) a[t][d] = row[d] * inv;
    }
    __syncthreads();

    for (int idx = t; idx < DIM * CH; idx += 256) {
        int o = idx / CH, d = idx % CH;
        float s = 0.f;
        #pragma unroll
        for (int c = 0; c < CH; c++)
            s += wproj[o * DIM + head * CH + c] * a[c][d];
        __nv_bfloat16 hi, lo;
        cvt_split(s, hi, lo);
        long adr = (long)b * 256 * DIM + o * DIM + head * CH + d;
        g_M_hi[adr] = hi;
        g_M_lo[adr] = lo;
    }
}

// ---------------------------------------------------------------------------
extern "C" void kernel_launch(void* const* d_in, const int* in_sizes, int n_in,
                              void* d_out, int out_size)
{
    const float* x     = (const float*)d_in[0];
    const float* wqkv  = (const float*)d_in[1];
    const float* wdw   = (const float*)d_in[2];
    const float* wproj = (const float*)d_in[3];
    const float* temp  = (const float*)d_in[4];
    float* out = (float*)d_out;

    cudaFuncSetAttribute(gemm_kernel<2>,
                         cudaFuncAttributeMaxDynamicSharedMemorySize, GEMM_SMEM(2));

    zero_kernel<<<36, 1024>>>();

    split_kernel<<<2048, 256>>>(x, 0, (long)B_ * DIM * HW / 4);
    split_kernel<<<64, 256>>>(wqkv, 1, (long)QKV * DIM / 4);

    // qkv GEMM: q/k tiles hi-only (y 0..2), v tiles full (y 3..4)
    gemm_kernel<1><<<dim3(HW / BN, 3, B_), 256, GEMM_SMEM(1)>>>(0, 0, nullptr);
    gemm_kernel<2><<<dim3(HW / BN, 2, B_), 256, GEMM_SMEM(2)>>>(0, 3, nullptr);

    dwconv_kernel<<<B_ * QKV * 2, 256>>>(wdw);

    attn_partial_kernel<<<dim3(ATTN_SPLIT, B_ * NH), 64>>>();

    softmax_m_kernel<<<B_ * NH, 256>>>(wproj, temp);

    // out GEMM: full 3-term
    gemm_kernel<2><<<dim3(HW / BN, 2, B_), 256, GEMM_SMEM(2)>>>(1, 0, out);
}

// round 14
// speedup vs baseline: 1.0886x; 1.0886x over previous
#include <cuda_runtime.h>
#include <cuda_bf16.h>
#include <math.h>
#include <stdint.h>

#define B_   8
#define DIM  192
#define QKV  576
#define NH   8
#define CH   24
#define H_   128
#define W_   128
#define HW   16384

// Scratch (device globals; zero-initialized bss)
__device__ __align__(16) __nv_bfloat16 g_x_hi[B_ * DIM * HW];
__device__ __align__(16) __nv_bfloat16 g_x_lo[B_ * DIM * HW];
__device__ __align__(16) __nv_bfloat16 g_w_hi[640 * DIM];          // 576 + pad
__device__ __align__(16) __nv_bfloat16 g_w_lo[640 * DIM];
__device__ __align__(16) __nv_bfloat16 g_qk   [B_ * 2 * DIM * HW]; // q/k (hi only)
__device__ __align__(16) __nv_bfloat16 g_v_hi [B_ * DIM * HW];
__device__ __align__(16) __nv_bfloat16 g_v_lo [B_ * DIM * HW];
__device__ __align__(16) __nv_bfloat16 g_dwqk [B_ * 2 * DIM * HW];
__device__ __align__(16) __nv_bfloat16 g_dwv_hi[B_ * DIM * HW];
__device__ __align__(16) __nv_bfloat16 g_dwv_lo[B_ * DIM * HW];
__device__ __align__(16) __nv_bfloat16 g_M_hi[B_ * 256 * DIM];     // 192 + pad rows
__device__ __align__(16) __nv_bfloat16 g_M_lo[B_ * 256 * DIM];
__device__ float g_ssq[B_ * DIM];
__device__ float g_ssk[B_ * DIM];
__device__ float g_S  [B_ * NH * CH * CH];

// ---------------------------------------------------------------------------
__global__ void zero_kernel() {
    int i = blockIdx.x * blockDim.x + threadIdx.x;
    if (i < B_ * NH * CH * CH) g_S[i] = 0.f;
    if (i < B_ * DIM) { g_ssq[i] = 0.f; g_ssk[i] = 0.f; }
}

__device__ __forceinline__ void cvt_split(float x, __nv_bfloat16 &hi, __nv_bfloat16 &lo) {
    hi = __float2bfloat16(x);
    lo = __float2bfloat16(x - __bfloat162float(hi));
}

// fp32 -> bf16 hi/lo planes. which: 0 -> x planes, 1 -> w planes
__global__ __launch_bounds__(256) void split_kernel(
    const float* __restrict__ src, int which, long n4)
{
    __nv_bfloat16* hi = which ? g_w_hi : g_x_hi;
    __nv_bfloat16* lo = which ? g_w_lo : g_x_lo;
    long i = blockIdx.x * (long)blockDim.x + threadIdx.x;
    long stride = (long)gridDim.x * blockDim.x;
    for (; i < n4; i += stride) {
        float4 v = ((const float4*)src)[i];
        __nv_bfloat16 h0,h1,h2,h3,l0,l1,l2,l3;
        cvt_split(v.x,h0,l0); cvt_split(v.y,h1,l1);
        cvt_split(v.z,h2,l2); cvt_split(v.w,h3,l3);
        ((__nv_bfloat162*)hi)[i*2]   = __nv_bfloat162(h0,h1);
        ((__nv_bfloat162*)hi)[i*2+1] = __nv_bfloat162(h2,h3);
        ((__nv_bfloat162*)lo)[i*2]   = __nv_bfloat162(l0,l1);
        ((__nv_bfloat162*)lo)[i*2+1] = __nv_bfloat162(l2,l3);
    }
}

// ---------------------------------------------------------------------------
// bf16 tensor-core GEMM, templated on plane count PL and BK tile BKT.
// PL=2: 3-term bf16x3.  PL=1: hi*hi only (BKT=64 -> 96 mma per barrier).
// BM=128 BN=128, 8 warps, warp tile 64x32, 2-stage cp.async.
// ---------------------------------------------------------------------------
#define BM 128
#define BN 128
#define LDB_S 136

__device__ __forceinline__ uint32_t cvta_s(const void* p) {
    return (uint32_t)__cvta_generic_to_shared(p);
}
__device__ __forceinline__ void cp_async16(uint32_t saddr, const void* gptr) {
    asm volatile("cp.async.cg.shared.global [%0], [%1], 16;" :: "r"(saddr), "l"(gptr));
}
__device__ __forceinline__ void ldsm4(uint32_t &r0, uint32_t &r1, uint32_t &r2,
                                      uint32_t &r3, uint32_t addr) {
    asm volatile("ldmatrix.sync.aligned.m8n8.x4.shared.b16 {%0,%1,%2,%3}, [%4];"
                 : "=r"(r0), "=r"(r1), "=r"(r2), "=r"(r3) : "r"(addr));
}
__device__ __forceinline__ void ldsm4t(uint32_t &r0, uint32_t &r1, uint32_t &r2,
                                       uint32_t &r3, uint32_t addr) {
    asm volatile("ldmatrix.sync.aligned.m8n8.x4.trans.shared.b16 {%0,%1,%2,%3}, [%4];"
                 : "=r"(r0), "=r"(r1), "=r"(r2), "=r"(r3) : "r"(addr));
}
__device__ __forceinline__ void mma16816(float c[4], uint32_t a0, uint32_t a1,
                                         uint32_t a2, uint32_t a3,
                                         uint32_t b0, uint32_t b1) {
    asm volatile(
        "mma.sync.aligned.m16n8k16.row.col.f32.bf16.bf16.f32 "
        "{%0,%1,%2,%3}, {%4,%5,%6,%7}, {%8,%9}, {%0,%1,%2,%3};"
        : "+f"(c[0]), "+f"(c[1]), "+f"(c[2]), "+f"(c[3])
        : "r"(a0), "r"(a1), "r"(a2), "r"(a3), "r"(b0), "r"(b1));
}

// smem bytes for PL planes, BK tile (2 stages)
#define GEMM_SMEM(PL, BKT) \
    ((2 * (PL) * (BM * ((BKT) + 8) + (BKT) * LDB_S)) * 2)

template <int PL, int BKT>
__global__ __launch_bounds__(256, 2) void gemm_kernel(
    int mode, int ybase, float* __restrict__ Cext)
{
    extern __shared__ __align__(16) __nv_bfloat16 smem[];
    constexpr int LDA  = BKT + 8;
    constexpr int APL  = BM * LDA;
    constexpr int BPL  = BKT * LDB_S;
    constexpr int NCH  = 16 * BKT;        // 16B chunks per plane per operand stage
    constexpr int NJ   = (BKT * PL) / 16; // fill loop count (per operand)
    const int b_base = 2 * PL * APL;

    const int z = blockIdx.z;
    const int by = ybase + blockIdx.y;
    const __nv_bfloat16 *Ahi, *Alo, *Bhi, *Blo;
    if (mode == 0) {
        Ahi = g_w_hi; Alo = g_w_lo;
        Bhi = g_x_hi + (long)z * DIM * HW;
        Blo = g_x_lo + (long)z * DIM * HW;
    } else {
        Ahi = g_M_hi + (long)z * 256 * DIM;
        Alo = g_M_lo + (long)z * 256 * DIM;
        Bhi = g_dwv_hi + (long)z * DIM * HW;
        Blo = g_dwv_lo + (long)z * DIM * HW;
    }
    Ahi += (long)by * BM * DIM;
    Alo += (long)by * BM * DIM;
    const int bcol = blockIdx.x * BN;

    const int t    = threadIdx.x;
    const int lane = t & 31;
    const int warp = t >> 5;
    const int wm   = (warp >> 2) * 64;
    const int wn   = (warp & 3) * 32;
    const int lr   = lane & 15;
    const int lc   = (lane >> 4) * 8;

    float acc[4][4][4];
    #pragma unroll
    for (int i = 0; i < 4; i++)
        #pragma unroll
        for (int j = 0; j < 4; j++)
            #pragma unroll
            for (int r = 0; r < 4; r++) acc[i][j][r] = 0.f;

    auto cpA = [&](int k0, int stage) {
        #pragma unroll
        for (int j = 0; j < NJ; j++) {
            int id  = t + 256 * j;
            int p   = id / NCH;
            int w   = id % NCH;
            int row = w / (BKT / 8);
            int cc  = w % (BKT / 8);
            const __nv_bfloat16* g = (p ? Alo : Ahi) + (long)row * DIM + k0 + cc * 8;
            __nv_bfloat16* s = smem + (stage * PL + p) * APL + row * LDA + cc * 8;
            cp_async16(cvta_s(s), g);
        }
    };
    auto cpB = [&](int k0, int stage) {
        #pragma unroll
        for (int j = 0; j < NJ; j++) {
            int id  = t + 256 * j;
            int p   = id / NCH;
            int w   = id % NCH;
            int row = w >> 4;
            int cc  = w & 15;
            const __nv_bfloat16* g = (p ? Blo : Bhi) +
                (long)(k0 + row) * HW + bcol + cc * 8;
            __nv_bfloat16* s = smem + b_base + (stage * PL + p) * BPL +
                               row * LDB_S + cc * 8;
            cp_async16(cvta_s(s), g);
        }
    };

    cpA(0, 0); cpB(0, 0);
    asm volatile("cp.async.commit_group;");

    const int NIT = DIM / BKT;
    for (int i = 0; i < NIT; i++) {
        const int stage = i & 1;
        if (i + 1 < NIT) {
            cpA((i + 1) * BKT, stage ^ 1);
            cpB((i + 1) * BKT, stage ^ 1);
            asm volatile("cp.async.commit_group;");
            asm volatile("cp.async.wait_group 1;");
        } else {
            asm volatile("cp.async.wait_group 0;");
        }
        __syncthreads();

        const __nv_bfloat16* As[2];
        const __nv_bfloat16* Bs[2];
        #pragma unroll
        for (int p = 0; p < PL; p++) {
            As[p] = smem + (stage * PL + p) * APL;
            Bs[p] = smem + b_base + (stage * PL + p) * BPL;
        }

        #pragma unroll
        for (int kk = 0; kk < BKT; kk += 16) {
            uint32_t a[PL][4][4];
            uint32_t b[PL][2][4];
            #pragma unroll
            for (int p = 0; p < PL; p++) {
                #pragma unroll
                for (int mt = 0; mt < 4; mt++)
                    ldsm4(a[p][mt][0], a[p][mt][1], a[p][mt][2], a[p][mt][3],
                          cvta_s(As[p] + (wm + mt * 16 + lr) * LDA + kk + lc));
                #pragma unroll
                for (int nc = 0; nc < 2; nc++)
                    ldsm4t(b[p][nc][0], b[p][nc][1], b[p][nc][2], b[p][nc][3],
                           cvta_s(Bs[p] + (kk + lr) * LDB_S + wn + nc * 16 + lc));
            }
            #pragma unroll
            for (int mt = 0; mt < 4; mt++)
                #pragma unroll
                for (int j = 0; j < 4; j++) {
                    uint32_t bh0 = b[0][j >> 1][(j & 1) * 2];
                    uint32_t bh1 = b[0][j >> 1][(j & 1) * 2 + 1];
                    mma16816(acc[mt][j], a[0][mt][0], a[0][mt][1], a[0][mt][2],
                             a[0][mt][3], bh0, bh1);
                    if constexpr (PL == 2) {
                        uint32_t bl0 = b[1][j >> 1][(j & 1) * 2];
                        uint32_t bl1 = b[1][j >> 1][(j & 1) * 2 + 1];
                        mma16816(acc[mt][j], a[0][mt][0], a[0][mt][1], a[0][mt][2],
                                 a[0][mt][3], bl0, bl1);
                        mma16816(acc[mt][j], a[1][mt][0], a[1][mt][1], a[1][mt][2],
                                 a[1][mt][3], bh0, bh1);
                    }
                }
        }
        __syncthreads();
    }

    const int er = lane >> 2;
    const int ec = (lane & 3) * 2;
    #pragma unroll
    for (int mt = 0; mt < 4; mt++) {
        const int g0 = by * BM + wm + mt * 16;
        if (mode == 1) {
            if (g0 < DIM) {
                float* Cb = Cext + (long)z * DIM * HW;
                #pragma unroll
                for (int j = 0; j < 4; j++) {
                    long base = (long)(g0 + er) * HW + bcol + wn + j * 8 + ec;
                    *(float2*)&Cb[base]          = make_float2(acc[mt][j][0], acc[mt][j][1]);
                    *(float2*)&Cb[base + 8 * HW] = make_float2(acc[mt][j][2], acc[mt][j][3]);
                }
            }
        } else if (g0 < 2 * DIM) {
            __nv_bfloat16* dst = g_qk + (long)z * 2 * DIM * HW;
            #pragma unroll
            for (int j = 0; j < 4; j++) {
                long base = (long)(g0 + er) * HW + bcol + wn + j * 8 + ec;
                *(__nv_bfloat162*)&dst[base] = __nv_bfloat162(
                    __float2bfloat16(acc[mt][j][0]), __float2bfloat16(acc[mt][j][1]));
                *(__nv_bfloat162*)&dst[base + 8 * HW] = __nv_bfloat162(
                    __float2bfloat16(acc[mt][j][2]), __float2bfloat16(acc[mt][j][3]));
            }
        } else if (g0 < 3 * DIM) {
            long voff = (long)z * DIM * HW + (long)(g0 - 2 * DIM) * HW;
            #pragma unroll
            for (int j = 0; j < 4; j++) {
                #pragma unroll
                for (int hrow = 0; hrow < 2; hrow++) {
                    long a2 = voff + (long)(er + hrow * 8) * HW + bcol + wn + j * 8 + ec;
                    float v0 = acc[mt][j][hrow * 2], v1 = acc[mt][j][hrow * 2 + 1];
                    __nv_bfloat16 h0,h1,l0,l1;
                    cvt_split(v0,h0,l0); cvt_split(v1,h1,l1);
                    *(__nv_bfloat162*)&g_v_hi[a2] = __nv_bfloat162(h0,h1);
                    *(__nv_bfloat162*)&g_v_lo[a2] = __nv_bfloat162(l0,l1);
                }
            }
        }
    }
}

// ---------------------------------------------------------------------------
// Depthwise 3x3, dilation 2, pad 2; branch-free inner via halo smem.
// (R10-measured version, reverted from R13 regression.)
// ---------------------------------------------------------------------------
#define IMW 132

__global__ __launch_bounds__(256) void dwconv_kernel(const float* __restrict__ wdw) {
    __shared__ float img[68 * IMW];
    __shared__ float warpsum[8];

    const int blk  = blockIdx.x;
    const int half = blk & 1;
    const int bc   = blk >> 1;
    const int b    = bc / QKV;
    const int ch   = bc % QKV;
    const int r0   = half * 64;
    const bool isqk = (ch < 2 * DIM);

    const int t = threadIdx.x;
    if (isqk) {
        const __nv_bfloat16* in = g_qk + ((long)b * 2 * DIM + ch) * HW;
        for (int i = t; i < 68 * IMW; i += 256) {
            int ry = i / IMW, rx = i - ry * IMW;
            int y = r0 - 2 + ry, x = rx - 2;
            img[i] = (y >= 0 && y < H_ && x >= 0 && x < W_)
                ? __bfloat162float(in[y * W_ + x]) : 0.f;
        }
    } else {
        long off = ((long)b * DIM + ch - 2 * DIM) * HW;
        const __nv_bfloat16* inh = g_v_hi + off;
        const __nv_bfloat16* inl = g_v_lo + off;
        for (int i = t; i < 68 * IMW; i += 256) {
            int ry = i / IMW, rx = i - ry * IMW;
            int y = r0 - 2 + ry, x = rx - 2;
            img[i] = (y >= 0 && y < H_ && x >= 0 && x < W_)
                ? __bfloat162float(inh[y * W_ + x]) +
                  __bfloat162float(inl[y * W_ + x])
                : 0.f;
        }
    }
    float w[9];
    #pragma unroll
    for (int i = 0; i < 9; i++) w[i] = wdw[ch * 9 + i];
    __syncthreads();

    const int x0  = (t & 31) * 4;
    const int yy0 = t >> 5;
    float ssq = 0.f;

    __nv_bfloat16* outqk = g_dwqk + ((long)b * 2 * DIM + (isqk ? ch : 0)) * HW;
    long voff = isqk ? 0 : ((long)b * DIM + ch - 2 * DIM) * HW;

    for (int yo = yy0; yo < 64; yo += 8) {
        const int y    = r0 + yo;
        const int srow = yo + 2;
        float o[4] = {0.f, 0.f, 0.f, 0.f};
        #pragma unroll
        for (int ky = 0; ky < 3; ky++) {
            const float* row = &img[(srow + 2 * ky - 2) * IMW + x0];
            float w0 = w[ky * 3], w1 = w[ky * 3 + 1], w2 = w[ky * 3 + 2];
            #pragma unroll
            for (int j = 0; j < 4; j++)
                o[j] += w0 * row[j] + w1 * row[j + 2] + w2 * row[j + 4];
        }
        if (isqk) {
            *(__nv_bfloat162*)&outqk[y * W_ + x0] =
                __nv_bfloat162(__float2bfloat16(o[0]), __float2bfloat16(o[1]));
            *(__nv_bfloat162*)&outqk[y * W_ + x0 + 2] =
                __nv_bfloat162(__float2bfloat16(o[2]), __float2bfloat16(o[3]));
            #pragma unroll
            for (int j = 0; j < 4; j++) ssq += o[j] * o[j];
        } else {
            __nv_bfloat16 h[4], l[4];
            #pragma unroll
            for (int j = 0; j < 4; j++) cvt_split(o[j], h[j], l[j]);
            long a = voff + y * W_ + x0;
            *(__nv_bfloat162*)&g_dwv_hi[a]     = __nv_bfloat162(h[0], h[1]);
            *(__nv_bfloat162*)&g_dwv_hi[a + 2] = __nv_bfloat162(h[2], h[3]);
            *(__nv_bfloat162*)&g_dwv_lo[a]     = __nv_bfloat162(l[0], l[1]);
            *(__nv_bfloat162*)&g_dwv_lo[a + 2] = __nv_bfloat162(l[2], l[3]);
        }
    }

    if (isqk) {
        #pragma unroll
        for (int off = 16; off; off >>= 1)
            ssq += __shfl_xor_sync(0xffffffffu, ssq, off);
        if ((t & 31) == 0) warpsum[t >> 5] = ssq;
        __syncthreads();
        if (t == 0) {
            float s = 0.f;
            #pragma unroll
            for (int i = 0; i < 8; i++) s += warpsum[i];
            float* dst = (ch < DIM) ? &g_ssq[b * DIM + ch]
                                    : &g_ssk[b * DIM + ch - DIM];
            atomicAdd(dst, s);
        }
    }
}

// ---------------------------------------------------------------------------
#define ATTN_SPLIT 64
#define ATTN_NB (HW / ATTN_SPLIT)   // 256

__global__ __launch_bounds__(64) void attn_partial_kernel() {
    __shared__ float qs[CH][68];
    __shared__ float ks[CH][68];

    const int bh   = blockIdx.y;
    const int b    = bh >> 3, head = bh & 7;
    const long qbase = ((long)b * 2 * DIM + head * CH) * HW;
    const long kbase = ((long)b * 2 * DIM + DIM + head * CH) * HW;
    const int nb = blockIdx.x * ATTN_NB;

    const int t  = threadIdx.x;
    const int cb = (t >> 3) * 3;
    const int db = (t & 7)  * 3;

    float acc[3][3] = {{0.f,0.f,0.f},{0.f,0.f,0.f},{0.f,0.f,0.f}};

    for (int c0 = 0; c0 < ATTN_NB; c0 += 64) {
        __syncthreads();
        for (int i = t; i < CH * 16; i += 64) {
            int row = i >> 4, c4 = (i & 15) * 4;
            uint2 uq = *(const uint2*)&g_dwqk[qbase + (long)row * HW + nb + c0 + c4];
            uint2 uk = *(const uint2*)&g_dwqk[kbase + (long)row * HW + nb + c0 + c4];
            __nv_bfloat162 q0 = *(__nv_bfloat162*)&uq.x;
            __nv_bfloat162 q1 = *(__nv_bfloat162*)&uq.y;
            __nv_bfloat162 k0 = *(__nv_bfloat162*)&uk.x;
            __nv_bfloat162 k1 = *(__nv_bfloat162*)&uk.y;
            qs[row][c4]     = __bfloat162float(q0.x);
            qs[row][c4 + 1] = __bfloat162float(q0.y);
            qs[row][c4 + 2] = __bfloat162float(q1.x);
            qs[row][c4 + 3] = __bfloat162float(q1.y);
            ks[row][c4]     = __bfloat162float(k0.x);
            ks[row][c4 + 1] = __bfloat162float(k0.y);
            ks[row][c4 + 2] = __bfloat162float(k1.x);
            ks[row][c4 + 3] = __bfloat162float(k1.y);
        }
        __syncthreads();
        #pragma unroll
        for (int nn = 0; nn < 64; nn += 4) {
            float4 q[3], k[3];
            #pragma unroll
            for (int i = 0; i < 3; i++) q[i] = *(float4*)&qs[cb + i][nn];
            #pragma unroll
            for (int j = 0; j < 3; j++) k[j] = *(float4*)&ks[db + j][nn];
            #pragma unroll
            for (int i = 0; i < 3; i++)
                #pragma unroll
                for (int j = 0; j < 3; j++)
                    acc[i][j] += q[i].x * k[j].x + q[i].y * k[j].y +
                                 q[i].z * k[j].z + q[i].w * k[j].w;
        }
    }
    #pragma unroll
    for (int i = 0; i < 3; i++)
        #pragma unroll
        for (int j = 0; j < 3; j++)
            atomicAdd(&g_S[(bh * CH + cb + i) * CH + db + j], acc[i][j]);
}

// ---------------------------------------------------------------------------
__global__ __launch_bounds__(256) void softmax_m_kernel(
    const float* __restrict__ wproj, const float* __restrict__ temperature)
{
    __shared__ float a[CH][CH];
    __shared__ float rq[CH], rk[CH];

    const int bh = blockIdx.x;
    const int b = bh >> 3, head = bh & 7;
    const int t = threadIdx.x;

    for (int i = t; i < CH * CH; i += 256)
        a[i / CH][i % CH] = g_S[bh * CH * CH + i];
    if (t < CH) {
        float nq = sqrtf(g_ssq[b * DIM + head * CH + t]);
        rq[t] = 1.f / fmaxf(nq, 1e-12f);
        float nk = sqrtf(g_ssk[b * DIM + head * CH + t]);
        rk[t] = 1.f / fmaxf(nk, 1e-12f);
    }
    __syncthreads();

    if (t < CH) {
        const float temp = temperature[head];
        float row[CH];
        float m = -1e30f;
        #pragma unroll
        for (int d = 0; d < CH; d++) {
            float v = a[t][d] * rq[t] * rk[d] * temp;
            row[d] = v;
            m = fmaxf(m, v);
        }
        float s = 0.f;
        #pragma unroll
        for (int d = 0; d < CH; d++) { row[d] = expf(row[d] - m); s += row[d]; }
        float inv = 1.f / s;
        #pragma unroll
        for (int d = 0; d < CH; d++) a[t][d] = row[d] * inv;
    }
    __syncthreads();

    for (int idx = t; idx < DIM * CH; idx += 256) {
        int o = idx / CH, d = idx % CH;
        float s = 0.f;
        #pragma unroll
        for (int c = 0; c < CH; c++)
            s += wproj[o * DIM + head * CH + c] * a[c][d];
        __nv_bfloat16 hi, lo;
        cvt_split(s, hi, lo);
        long adr = (long)b * 256 * DIM + o * DIM + head * CH + d;
        g_M_hi[adr] = hi;
        g_M_lo[adr] = lo;
    }
}

// ---------------------------------------------------------------------------
extern "C" void kernel_launch(void* const* d_in, const int* in_sizes, int n_in,
                              void* d_out, int out_size)
{
    const float* x     = (const float*)d_in[0];
    const float* wqkv  = (const float*)d_in[1];
    const float* wdw   = (const float*)d_in[2];
    const float* wproj = (const float*)d_in[3];
    const float* temp  = (const float*)d_in[4];
    float* out = (float*)d_out;

    cudaFuncSetAttribute((const void*)gemm_kernel<2, 32>,
                         cudaFuncAttributeMaxDynamicSharedMemorySize,
                         GEMM_SMEM(2, 32));
    cudaFuncSetAttribute((const void*)gemm_kernel<1, 64>,
                         cudaFuncAttributeMaxDynamicSharedMemorySize,
                         GEMM_SMEM(1, 64));

    zero_kernel<<<36, 1024>>>();

    split_kernel<<<2048, 256>>>(x, 0, (long)B_ * DIM * HW / 4);
    split_kernel<<<64, 256>>>(wqkv, 1, (long)QKV * DIM / 4);

    // qkv GEMM: q/k tiles hi-only BK=64 (y 0..2), v tiles full BK=32 (y 3..4)
    gemm_kernel<1, 64><<<dim3(HW / BN, 3, B_), 256, GEMM_SMEM(1, 64)>>>(0, 0, nullptr);
    gemm_kernel<2, 32><<<dim3(HW / BN, 2, B_), 256, GEMM_SMEM(2, 32)>>>(0, 3, nullptr);

    dwconv_kernel<<<B_ * QKV * 2, 256>>>(wdw);

    attn_partial_kernel<<<dim3(ATTN_SPLIT, B_ * NH), 64>>>();

    softmax_m_kernel<<<B_ * NH, 256>>>(wproj, temp);

    // out GEMM: full 3-term
    gemm_kernel<2, 32><<<dim3(HW / BN, 2, B_), 256, GEMM_SMEM(2, 32)>>>(1, 0, out);
}